// round 1
// baseline (speedup 1.0000x reference)
#include <cuda_runtime.h>
#include <math.h>

#define TT 4096
#define DD 1024
#define HH 768
#define EE 23
#define KTOP 3

// ---------------- device scratch (static allocations, allowed) ----------------
__device__ int   g_cnt[EE];
__device__ float g_psum[EE];
__device__ int   g_tok[EE * TT];
__device__ float g_wt[EE * TT];
__device__ float g_h[(size_t)EE * TT * HH];   // per-expert hidden, padded layout (~289 MB)
__device__ float g_hs[(size_t)TT * HH];       // shared-expert hidden (~12.6 MB)

// ---------------- zero accumulators each launch ----------------
__global__ void zero_k() {
    int i = threadIdx.x;
    if (i < EE) { g_cnt[i] = 0; g_psum[i] = 0.f; }
}

// ---------------- gating: one block per token, warp per expert ----------------
__global__ __launch_bounds__(736) void gating_k(
    const float* __restrict__ x, const float* __restrict__ gW,
    const float* __restrict__ gb, const float* __restrict__ bias)
{
    int t = blockIdx.x;
    __shared__ float xs[DD];
    __shared__ float sg[EE];
    for (int i = threadIdx.x; i < DD; i += blockDim.x) xs[i] = x[(size_t)t * DD + i];
    __syncthreads();
    int warp = threadIdx.x >> 5, lane = threadIdx.x & 31;
    if (warp < EE) {
        float s = 0.f;
        for (int d = lane; d < DD; d += 32) s += xs[d] * gW[d * EE + warp];
        #pragma unroll
        for (int o = 16; o; o >>= 1) s += __shfl_xor_sync(0xffffffffu, s, o);
        if (lane == 0) sg[warp] = 1.f / (1.f + expf(-(s + gb[warp])));
    }
    __syncthreads();
    if (threadIdx.x == 0) {
        float g[EE]; float sumg = 0.f;
        #pragma unroll
        for (int e = 0; e < EE; e++) { g[e] = sg[e]; sumg += g[e]; }
        int idx[KTOP]; float wv[KTOP];
        bool used[EE];
        #pragma unroll
        for (int e = 0; e < EE; e++) used[e] = false;
        #pragma unroll
        for (int k = 0; k < KTOP; k++) {
            float best = -1e30f; int bi = 0;
            for (int e = 0; e < EE; e++) {
                if (!used[e]) {
                    float v = g[e] + bias[e];
                    if (v > best) { best = v; bi = e; }
                }
            }
            used[bi] = true; idx[k] = bi; wv[k] = g[bi];
        }
        float ws = wv[0] + wv[1] + wv[2];
        #pragma unroll
        for (int k = 0; k < KTOP; k++) {
            int e = idx[k];
            int slot = atomicAdd(&g_cnt[e], 1);
            g_tok[e * TT + slot] = t;
            g_wt[e * TT + slot]  = wv[k] / ws;
        }
        float inv = 1.f / sumg;
        #pragma unroll
        for (int e = 0; e < EE; e++) atomicAdd(&g_psum[e], g[e] * inv);
    }
}

// ---------------- fused FFN GEMM template ----------------
// MOE=1: per-expert (blockIdx.z = expert, gather/scatter by token list)
// FIRST=1: X[M,Kdim] @ W[Kdim,N] + b, exact GELU, store to hidden buffer
// FIRST=0: H[M,Kdim] @ W[Kdim,N] + b; MOE: out[tok] += w*val (atomic); else out[m] = val
template<bool MOE, bool FIRST>
__global__ __launch_bounds__(256) void ffn_k(
    const float* __restrict__ x,      // input activations (used when FIRST)
    const float* __restrict__ W,      // weight base
    const float* __restrict__ b,      // bias base
    float* __restrict__ out)          // d_out (used when !FIRST)
{
    constexpr int BM = 128, BN = 128, BK = 8;
    constexpr int Kdim = FIRST ? DD : HH;
    constexpr int Ndim = FIRST ? HH : DD;

    const int e   = MOE ? blockIdx.z : 0;
    const int cnt = MOE ? g_cnt[e] : TT;
    const int m0  = blockIdx.y * BM;
    if (m0 >= cnt) return;
    const int n0  = blockIdx.x * BN;

    __shared__ float As[BK][BM];
    __shared__ float Bs[BK][BN];
    __shared__ int   s_tok[BM];
    __shared__ float s_wt[BM];

    const float* Wexp = MOE ? (W + (size_t)e * Kdim * Ndim) : W;
    const float* bexp = MOE ? (b + (size_t)e * Ndim) : b;

    if (MOE) {
        for (int i = threadIdx.x; i < BM; i += 256) {
            int m = m0 + i;
            s_tok[i] = (m < cnt) ? g_tok[e * TT + m] : 0;
            s_wt[i]  = (m < cnt) ? g_wt[e * TT + m] : 0.f;
        }
        __syncthreads();
    }

    const int tid = threadIdx.x;
    const int tx = tid & 15, ty = tid >> 4;
    const int a_m = tid >> 1;
    const int a_k = (tid & 1) * 4;
    const int b_k = tid >> 5;
    const int b_n = (tid & 31) * 4;

    // A row pointer (safe even for padded rows: token 0 / in-bounds stale data; stores are guarded)
    const float* arow;
    if (FIRST) {
        int row = MOE ? s_tok[a_m] : (m0 + a_m);
        arow = x + (size_t)row * DD;
    } else {
        if (MOE) arow = g_h + ((size_t)e * TT + (m0 + a_m)) * HH;
        else     arow = g_hs + (size_t)(m0 + a_m) * HH;
    }

    float acc[8][8];
    #pragma unroll
    for (int i = 0; i < 8; i++)
        #pragma unroll
        for (int j = 0; j < 8; j++) acc[i][j] = 0.f;

    for (int k0 = 0; k0 < Kdim; k0 += BK) {
        float4 av = *(const float4*)(arow + k0 + a_k);
        float4 bv = *(const float4*)(Wexp + (size_t)(k0 + b_k) * Ndim + n0 + b_n);
        As[a_k + 0][a_m] = av.x;
        As[a_k + 1][a_m] = av.y;
        As[a_k + 2][a_m] = av.z;
        As[a_k + 3][a_m] = av.w;
        *(float4*)&Bs[b_k][b_n] = bv;
        __syncthreads();
        #pragma unroll
        for (int k = 0; k < BK; k++) {
            float4 a0 = *(const float4*)&As[k][ty * 8];
            float4 a1 = *(const float4*)&As[k][ty * 8 + 4];
            float4 b0 = *(const float4*)&Bs[k][tx * 8];
            float4 b1 = *(const float4*)&Bs[k][tx * 8 + 4];
            float ra[8] = {a0.x, a0.y, a0.z, a0.w, a1.x, a1.y, a1.z, a1.w};
            float rb[8] = {b0.x, b0.y, b0.z, b0.w, b1.x, b1.y, b1.z, b1.w};
            #pragma unroll
            for (int i = 0; i < 8; i++)
                #pragma unroll
                for (int j = 0; j < 8; j++) acc[i][j] += ra[i] * rb[j];
        }
        __syncthreads();
    }

    float bb[8];
    #pragma unroll
    for (int j = 0; j < 8; j++) bb[j] = bexp[n0 + tx * 8 + j];

    #pragma unroll
    for (int i = 0; i < 8; i++) {
        int m = m0 + ty * 8 + i;
        if (MOE && m >= cnt) continue;
        #pragma unroll
        for (int j = 0; j < 8; j++) {
            float v = acc[i][j] + bb[j];
            int n = n0 + tx * 8 + j;
            if (FIRST) {
                v = 0.5f * v * (1.f + erff(v * 0.70710678118654752f));
                if (MOE) g_h[((size_t)e * TT + m) * HH + n] = v;
                else     g_hs[(size_t)m * HH + n] = v;
            } else {
                if (MOE) {
                    atomicAdd(&out[(size_t)s_tok[ty * 8 + i] * DD + n], s_wt[ty * 8 + i] * v);
                } else {
                    out[(size_t)m * DD + n] = v;   // overwrites poison
                }
            }
        }
    }
}

// ---------------- finalize: aux loss + counts tail ----------------
__global__ void finalize_k(float* __restrict__ out, int out_size) {
    if (blockIdx.x == 0 && threadIdx.x == 0) {
        float aux = 0.f;
        for (int e = 0; e < EE; e++) {
            float P = g_psum[e] / (float)TT;
            float F = (float)EE * (float)g_cnt[e] / (float)(KTOP * TT);
            aux += P * F;
        }
        const int base = TT * DD;
        if (out_size >= base + 1) out[base] = aux;
        for (int e = 0; e < EE; e++)
            if (out_size >= base + 2 + e) out[base + 1 + e] = (float)g_cnt[e];
    }
}

extern "C" void kernel_launch(void* const* d_in, const int* in_sizes, int n_in,
                              void* d_out, int out_size) {
    const float* x    = (const float*)d_in[0];
    const float* gW   = (const float*)d_in[1];
    const float* gb   = (const float*)d_in[2];
    const float* bias = (const float*)d_in[3];
    const float* W1   = (const float*)d_in[4];
    const float* b1   = (const float*)d_in[5];
    const float* W2   = (const float*)d_in[6];
    const float* b2   = (const float*)d_in[7];
    const float* sW1  = (const float*)d_in[8];
    const float* sb1  = (const float*)d_in[9];
    const float* sW2  = (const float*)d_in[10];
    const float* sb2  = (const float*)d_in[11];
    float* out = (float*)d_out;

    zero_k<<<1, 32>>>();
    gating_k<<<TT, 736>>>(x, gW, gb, bias);

    // MoE GEMM1: gather + GELU -> g_h
    ffn_k<true, true><<<dim3(HH / 128, TT / 128, EE), 256>>>(x, W1, b1, nullptr);
    // Shared GEMM1 -> g_hs
    ffn_k<false, true><<<dim3(HH / 128, TT / 128, 1), 256>>>(x, sW1, sb1, nullptr);
    // Shared GEMM2: writes out (initializes every element)
    ffn_k<false, false><<<dim3(DD / 128, TT / 128, 1), 256>>>(nullptr, sW2, sb2, out);
    // MoE GEMM2: weighted atomic combine into out
    ffn_k<true, false><<<dim3(DD / 128, TT / 128, EE), 256>>>(nullptr, W2, b2, out);

    finalize_k<<<1, 32>>>(out, out_size);
}

// round 3
// speedup vs baseline: 1.1105x; 1.1105x over previous
#include <cuda_runtime.h>
#include <cstdint>
#include <math.h>

#define TT 4096
#define DD 1024
#define HH 768
#define EE 23
#define KTOP 3

typedef unsigned long long ull;

// ---------------- device scratch ----------------
__device__ int   g_cnt[EE];
__device__ float g_psum[EE];
__device__ int   g_tok[EE * TT];
__device__ float g_wt[EE * TT];
__device__ float g_h[(size_t)EE * TT * HH];   // per-expert hidden (padded layout)
__device__ float g_hs[(size_t)TT * HH];       // shared-expert hidden

// ---------------- helpers ----------------
__device__ __forceinline__ ull pack2(float x) {
    ull r; asm("mov.b64 %0, {%1, %1};" : "=l"(r) : "f"(x)); return r;
}
__device__ __forceinline__ float2 unpk(ull v) {
    float2 f; asm("mov.b64 {%0, %1}, %2;" : "=f"(f.x), "=f"(f.y) : "l"(v)); return f;
}
__device__ __forceinline__ void ffma2(ull& d, ull a, ull b) {
    asm("fma.rn.f32x2 %0, %1, %2, %0;" : "+l"(d) : "l"(a), "l"(b));
}
__device__ __forceinline__ void cp16(unsigned int s, const void* g) {
    asm volatile("cp.async.cg.shared.global [%0], [%1], 16;" :: "r"(s), "l"(g));
}
__device__ __forceinline__ void cp_commit() { asm volatile("cp.async.commit_group;"); }
__device__ __forceinline__ void cp_wait0()  { asm volatile("cp.async.wait_group 0;"); }

// ---------------- zero accumulators ----------------
__global__ void zero_k() {
    int i = threadIdx.x;
    if (i < EE) { g_cnt[i] = 0; g_psum[i] = 0.f; }
}

// ---------------- gating ----------------
__global__ __launch_bounds__(736) void gating_k(
    const float* __restrict__ x, const float* __restrict__ gW,
    const float* __restrict__ gb, const float* __restrict__ bias)
{
    int t = blockIdx.x;
    __shared__ float xs[DD];
    __shared__ float sg[EE];
    for (int i = threadIdx.x; i < DD; i += blockDim.x) xs[i] = x[(size_t)t * DD + i];
    __syncthreads();
    int warp = threadIdx.x >> 5, lane = threadIdx.x & 31;
    if (warp < EE) {
        float s = 0.f;
        for (int d = lane; d < DD; d += 32) s += xs[d] * gW[d * EE + warp];
        #pragma unroll
        for (int o = 16; o; o >>= 1) s += __shfl_xor_sync(0xffffffffu, s, o);
        if (lane == 0) sg[warp] = 1.f / (1.f + expf(-(s + gb[warp])));
    }
    __syncthreads();
    if (threadIdx.x == 0) {
        float g[EE]; float sumg = 0.f;
        #pragma unroll
        for (int e = 0; e < EE; e++) { g[e] = sg[e]; sumg += g[e]; }
        int idx[KTOP]; float wv[KTOP];
        bool used[EE];
        #pragma unroll
        for (int e = 0; e < EE; e++) used[e] = false;
        #pragma unroll
        for (int k = 0; k < KTOP; k++) {
            float best = -1e30f; int bi = 0;
            for (int e = 0; e < EE; e++) {
                if (!used[e]) {
                    float v = g[e] + bias[e];
                    if (v > best) { best = v; bi = e; }
                }
            }
            used[bi] = true; idx[k] = bi; wv[k] = g[bi];
        }
        float ws = wv[0] + wv[1] + wv[2];
        #pragma unroll
        for (int k = 0; k < KTOP; k++) {
            int e = idx[k];
            int slot = atomicAdd(&g_cnt[e], 1);
            g_tok[e * TT + slot] = t;
            g_wt[e * TT + slot]  = wv[k] / ws;
        }
        float inv = 1.f / sumg;
        #pragma unroll
        for (int e = 0; e < EE; e++) atomicAdd(&g_psum[e], g[e] * inv);
    }
}

// ---------------- pipelined FFN GEMM (f32x2, cp.async double-buffer) ----------------
template<bool MOE, bool FIRST>
__global__ __launch_bounds__(256, 2) void ffn_k(
    const float* __restrict__ x,
    const float* __restrict__ W,
    const float* __restrict__ b,
    float* __restrict__ out)
{
    constexpr int BM = 128, BN = 128, BK = 16;
    constexpr int Kdim = FIRST ? DD : HH;
    constexpr int Ndim = FIRST ? HH : DD;
    constexpr int NT = Kdim / BK;

    const int e   = MOE ? blockIdx.z : 0;
    const int cnt = MOE ? g_cnt[e] : TT;
    const int m0  = blockIdx.y * BM;
    if (m0 >= cnt) return;
    const int n0  = blockIdx.x * BN;

    __shared__ float As[2][BK][BM];
    __shared__ float Bs[2][BK][BN];
    __shared__ int   s_tok[BM];
    __shared__ float s_wt[BM];

    const float* Wexp = MOE ? (W + (size_t)e * Kdim * Ndim) : W;
    const float* bexp = MOE ? (b + (size_t)e * Ndim) : b;

    const int tid = threadIdx.x;

    if (MOE) {
        for (int i = tid; i < BM; i += 256) {
            int m = m0 + i;
            s_tok[i] = (m < cnt) ? g_tok[e * TT + m] : 0;
            s_wt[i]  = (m < cnt) ? g_wt[e * TT + m] : 0.f;
        }
        __syncthreads();
    }

    // A staging: each thread owns 8 consecutive k of one row
    const int a_m = tid >> 1;
    const int a_k = (tid & 1) * 8;
    // B cp.async: each thread copies 32B of one k-row
    const int b_k = tid >> 4;
    const int b_n = (tid & 15) * 8;

    const float* arow;
    if (FIRST) {
        int row = MOE ? s_tok[a_m] : (m0 + a_m);
        arow = x + (size_t)row * DD;
    } else {
        if (MOE) arow = g_h + ((size_t)e * TT + (m0 + a_m)) * HH;
        else     arow = g_hs + (size_t)(m0 + a_m) * HH;
    }
    const float* bptr = Wexp + (size_t)b_k * Ndim + n0 + b_n;

    const int tx = tid & 15, ty = tid >> 4;

    ull acc[8][4];
    #pragma unroll
    for (int i = 0; i < 8; i++)
        #pragma unroll
        for (int j = 0; j < 4; j++) acc[i][j] = 0ULL;

    unsigned int bs_base[2];
    bs_base[0] = (unsigned int)__cvta_generic_to_shared(&Bs[0][b_k][b_n]);
    bs_base[1] = (unsigned int)__cvta_generic_to_shared(&Bs[1][b_k][b_n]);

    // ---- prologue: tile 0 ----
    {
        float4 av0 = *(const float4*)(arow + a_k);
        float4 av1 = *(const float4*)(arow + a_k + 4);
        cp16(bs_base[0],      bptr);
        cp16(bs_base[0] + 16, bptr + 4);
        cp_commit();
        As[0][a_k + 0][a_m] = av0.x; As[0][a_k + 1][a_m] = av0.y;
        As[0][a_k + 2][a_m] = av0.z; As[0][a_k + 3][a_m] = av0.w;
        As[0][a_k + 4][a_m] = av1.x; As[0][a_k + 5][a_m] = av1.y;
        As[0][a_k + 6][a_m] = av1.z; As[0][a_k + 7][a_m] = av1.w;
        cp_wait0();
        __syncthreads();
    }

    for (int kt = 0; kt < NT; kt++) {
        const int cur = kt & 1, nxt = cur ^ 1;
        const bool hn = (kt + 1 < NT);
        float4 av0, av1;
        if (hn) {
            const float* an = arow + (kt + 1) * BK + a_k;
            av0 = *(const float4*)(an);
            av1 = *(const float4*)(an + 4);
            const float* bn = bptr + (size_t)(kt + 1) * BK * Ndim;
            cp16(bs_base[nxt],      bn);
            cp16(bs_base[nxt] + 16, bn + 4);
            cp_commit();
        }

        #pragma unroll
        for (int k = 0; k < BK; k++) {
            const float4* ap4 = (const float4*)&As[cur][k][ty * 8];
            float4 A0 = ap4[0], A1 = ap4[1];
            ull ar[8] = {pack2(A0.x), pack2(A0.y), pack2(A0.z), pack2(A0.w),
                         pack2(A1.x), pack2(A1.y), pack2(A1.z), pack2(A1.w)};
            ulonglong2 Bv0 = *(const ulonglong2*)&Bs[cur][k][tx * 8];
            ulonglong2 Bv1 = *(const ulonglong2*)&Bs[cur][k][tx * 8 + 4];
            ull br[4] = {Bv0.x, Bv0.y, Bv1.x, Bv1.y};
            #pragma unroll
            for (int i = 0; i < 8; i++)
                #pragma unroll
                for (int j = 0; j < 4; j++)
                    ffma2(acc[i][j], ar[i], br[j]);
        }

        if (hn) {
            As[nxt][a_k + 0][a_m] = av0.x; As[nxt][a_k + 1][a_m] = av0.y;
            As[nxt][a_k + 2][a_m] = av0.z; As[nxt][a_k + 3][a_m] = av0.w;
            As[nxt][a_k + 4][a_m] = av1.x; As[nxt][a_k + 5][a_m] = av1.y;
            As[nxt][a_k + 6][a_m] = av1.z; As[nxt][a_k + 7][a_m] = av1.w;
        }
        cp_wait0();
        __syncthreads();
    }

    float bb[8];
    #pragma unroll
    for (int j = 0; j < 8; j++) bb[j] = bexp[n0 + tx * 8 + j];

    #pragma unroll
    for (int i = 0; i < 8; i++) {
        int m = m0 + ty * 8 + i;
        if (MOE && m >= cnt) continue;
        #pragma unroll
        for (int jp = 0; jp < 4; jp++) {
            float2 v2 = unpk(acc[i][jp]);
            #pragma unroll
            for (int h = 0; h < 2; h++) {
                int j = jp * 2 + h;
                float v = (h ? v2.y : v2.x) + bb[j];
                int n = n0 + tx * 8 + j;
                if (FIRST) {
                    v = 0.5f * v * (1.f + erff(v * 0.70710678118654752f));
                    if (MOE) g_h[((size_t)e * TT + m) * HH + n] = v;
                    else     g_hs[(size_t)m * HH + n] = v;
                } else {
                    if (MOE) {
                        atomicAdd(&out[(size_t)s_tok[ty * 8 + i] * DD + n],
                                  s_wt[ty * 8 + i] * v);
                    } else {
                        out[(size_t)m * DD + n] = v;
                    }
                }
            }
        }
    }
}

// ---------------- finalize ----------------
__global__ void finalize_k(float* __restrict__ out, int out_size) {
    if (blockIdx.x == 0 && threadIdx.x == 0) {
        float aux = 0.f;
        for (int e = 0; e < EE; e++) {
            float P = g_psum[e] / (float)TT;
            float F = (float)EE * (float)g_cnt[e] / (float)(KTOP * TT);
            aux += P * F;
        }
        const int base = TT * DD;
        if (out_size >= base + 1) out[base] = aux;
        for (int e = 0; e < EE; e++)
            if (out_size >= base + 2 + e) out[base + 1 + e] = (float)g_cnt[e];
    }
}

extern "C" void kernel_launch(void* const* d_in, const int* in_sizes, int n_in,
                              void* d_out, int out_size) {
    const float* x    = (const float*)d_in[0];
    const float* gW   = (const float*)d_in[1];
    const float* gb   = (const float*)d_in[2];
    const float* bias = (const float*)d_in[3];
    const float* W1   = (const float*)d_in[4];
    const float* b1   = (const float*)d_in[5];
    const float* W2   = (const float*)d_in[6];
    const float* b2   = (const float*)d_in[7];
    const float* sW1  = (const float*)d_in[8];
    const float* sb1  = (const float*)d_in[9];
    const float* sW2  = (const float*)d_in[10];
    const float* sb2  = (const float*)d_in[11];
    float* out = (float*)d_out;

    zero_k<<<1, 32>>>();
    gating_k<<<TT, 736>>>(x, gW, gb, bias);

    ffn_k<true, true><<<dim3(HH / 128, TT / 128, EE), 256>>>(x, W1, b1, nullptr);
    ffn_k<false, true><<<dim3(HH / 128, TT / 128, 1), 256>>>(x, sW1, sb1, nullptr);
    ffn_k<false, false><<<dim3(DD / 128, TT / 128, 1), 256>>>(nullptr, sW2, sb2, out);
    ffn_k<true, false><<<dim3(DD / 128, TT / 128, EE), 256>>>(nullptr, W2, b2, out);

    finalize_k<<<1, 32>>>(out, out_size);
}

// round 12
// speedup vs baseline: 1.1234x; 1.0116x over previous
#include <cuda_runtime.h>
#include <cstdint>
#include <math.h>

#define TT 4096
#define DD 1024
#define HH 768
#define EE 23
#define KTOP 3

// ---------------- device scratch (same set as R3, which passed) ----------------
__device__ int   g_cnt[EE];
__device__ float g_psum[EE];
__device__ int   g_tok[EE * TT];
__device__ float g_wt[EE * TT];
__device__ float g_h[(size_t)EE * TT * HH];   // per-expert hidden (padded layout)
__device__ float g_hs[(size_t)TT * HH];       // shared-expert hidden

// ---------------- helpers ----------------
__device__ __forceinline__ void cp16(unsigned s, const void* g) {
    asm volatile("cp.async.cg.shared.global [%0], [%1], 16;" :: "r"(s), "l"(g));
}
__device__ __forceinline__ void cp_commit() { asm volatile("cp.async.commit_group;"); }
template<int N> __device__ __forceinline__ void cp_wait() {
    asm volatile("cp.async.wait_group %0;" :: "n"(N));
}

// ---------------- zero accumulators ----------------
__global__ void zero_k() {
    int i = threadIdx.x;
    if (i < EE) { g_cnt[i] = 0; g_psum[i] = 0.f; }
}

// ---------------- gating (verbatim from R3) ----------------
__global__ __launch_bounds__(736) void gating_k(
    const float* __restrict__ x, const float* __restrict__ gW,
    const float* __restrict__ gb, const float* __restrict__ bias)
{
    int t = blockIdx.x;
    __shared__ float xs[DD];
    __shared__ float sg[EE];
    for (int i = threadIdx.x; i < DD; i += blockDim.x) xs[i] = x[(size_t)t * DD + i];
    __syncthreads();
    int warp = threadIdx.x >> 5, lane = threadIdx.x & 31;
    if (warp < EE) {
        float s = 0.f;
        for (int d = lane; d < DD; d += 32) s += xs[d] * gW[d * EE + warp];
        #pragma unroll
        for (int o = 16; o; o >>= 1) s += __shfl_xor_sync(0xffffffffu, s, o);
        if (lane == 0) sg[warp] = 1.f / (1.f + expf(-(s + gb[warp])));
    }
    __syncthreads();
    if (threadIdx.x == 0) {
        float g[EE]; float sumg = 0.f;
        #pragma unroll
        for (int e = 0; e < EE; e++) { g[e] = sg[e]; sumg += g[e]; }
        int idx[KTOP]; float wv[KTOP];
        bool used[EE];
        #pragma unroll
        for (int e = 0; e < EE; e++) used[e] = false;
        #pragma unroll
        for (int k = 0; k < KTOP; k++) {
            float best = -1e30f; int bi = 0;
            for (int e = 0; e < EE; e++) {
                if (!used[e]) {
                    float v = g[e] + bias[e];
                    if (v > best) { best = v; bi = e; }
                }
            }
            used[bi] = true; idx[k] = bi; wv[k] = g[bi];
        }
        float ws = wv[0] + wv[1] + wv[2];
        #pragma unroll
        for (int k = 0; k < KTOP; k++) {
            int e = idx[k];
            int slot = atomicAdd(&g_cnt[e], 1);
            g_tok[e * TT + slot] = t;
            g_wt[e * TT + slot]  = wv[k] / ws;
        }
        float inv = 1.f / sumg;
        #pragma unroll
        for (int e = 0; e < EE; e++) atomicAdd(&g_psum[e], g[e] * inv);
    }
}

// ---------------- FFN GEMM: all-cp.async double buffer, plain FFMA ----------------
// 128x128 tile, 256 threads, 8x8 acc per thread, BK=16.
// As[st][m][k] row-major (64B rows), Bs[st][k][n].
template<bool MOE, bool FIRST>
__global__ __launch_bounds__(256, 2) void ffn_k(
    const float* __restrict__ x,
    const float* __restrict__ W,
    const float* __restrict__ b,
    float* __restrict__ out)
{
    constexpr int BM = 128, BN = 128, BK = 16;
    constexpr int Kdim = FIRST ? DD : HH;
    constexpr int Ndim = FIRST ? HH : DD;
    constexpr int NT = Kdim / BK;

    const int e   = MOE ? blockIdx.z : 0;
    const int cnt = MOE ? g_cnt[e] : TT;
    const int m0  = blockIdx.y * BM;
    if (m0 >= cnt) return;
    const int n0  = blockIdx.x * BN;
    const int tid = threadIdx.x;

    __shared__ float As[2][BM][BK];
    __shared__ float Bs[2][BK][BN];
    __shared__ int   s_tok[BM];
    __shared__ float s_wt[BM];

    const float* Wexp = MOE ? (W + (size_t)e * Kdim * Ndim) : W;
    const float* bexp = MOE ? (b + (size_t)e * Ndim) : b;

    if (MOE) {
        for (int i = tid; i < BM; i += 256) {
            int m = m0 + i;
            s_tok[i] = (m < cnt) ? g_tok[e * TT + m] : 0;
            s_wt[i]  = (m < cnt) ? g_wt[e * TT + m] : 0.f;
        }
        __syncthreads();
    }

    // loader mapping: A row a_m (0..127), 8 floats at a_k; B row b_k (0..15), 8 floats at b_n
    const int a_m = tid >> 1;
    const int a_k = (tid & 1) * 8;
    const int b_k = tid >> 4;
    const int b_n = (tid & 15) * 8;

    const float* arow;
    if (FIRST) {
        int row = MOE ? s_tok[a_m] : (m0 + a_m);
        arow = x + (size_t)row * DD;
    } else {
        if (MOE) arow = g_h + ((size_t)e * TT + (m0 + a_m)) * HH;
        else     arow = g_hs + (size_t)(m0 + a_m) * HH;
    }
    const float* brow = Wexp + (size_t)b_k * Ndim + n0 + b_n;

    unsigned asd[2], bsd[2];
    asd[0] = (unsigned)__cvta_generic_to_shared(&As[0][a_m][a_k]);
    asd[1] = (unsigned)__cvta_generic_to_shared(&As[1][a_m][a_k]);
    bsd[0] = (unsigned)__cvta_generic_to_shared(&Bs[0][b_k][b_n]);
    bsd[1] = (unsigned)__cvta_generic_to_shared(&Bs[1][b_k][b_n]);

    auto load_chunk = [&](int kt, int st) {
        const float* as = arow + kt * BK + a_k;
        const float* bs = brow + (size_t)kt * BK * Ndim;
        cp16(asd[st],      as);
        cp16(asd[st] + 16, as + 4);
        cp16(bsd[st],      bs);
        cp16(bsd[st] + 16, bs + 4);
        cp_commit();
    };

    const int tx = tid & 15, ty = tid >> 4;

    float acc[8][8];
    #pragma unroll
    for (int i = 0; i < 8; i++)
        #pragma unroll
        for (int j = 0; j < 8; j++) acc[i][j] = 0.f;

    // prologue
    load_chunk(0, 0);
    cp_wait<0>();
    __syncthreads();

    #pragma unroll 1
    for (int kt = 0; kt < NT; kt++) {
        const int cur = kt & 1, nxt = cur ^ 1;
        if (kt + 1 < NT) load_chunk(kt + 1, nxt);

        #pragma unroll
        for (int k4 = 0; k4 < 4; k4++) {
            float a[8][4];
            #pragma unroll
            for (int i = 0; i < 8; i++) {
                float4 v = *(const float4*)&As[cur][ty * 8 + i][k4 * 4];
                a[i][0] = v.x; a[i][1] = v.y; a[i][2] = v.z; a[i][3] = v.w;
            }
            #pragma unroll
            for (int kk = 0; kk < 4; kk++) {
                float4 b0 = *(const float4*)&Bs[cur][k4 * 4 + kk][tx * 8];
                float4 b1 = *(const float4*)&Bs[cur][k4 * 4 + kk][tx * 8 + 4];
                float rb[8] = {b0.x, b0.y, b0.z, b0.w, b1.x, b1.y, b1.z, b1.w};
                #pragma unroll
                for (int i = 0; i < 8; i++)
                    #pragma unroll
                    for (int j = 0; j < 8; j++)
                        acc[i][j] += a[i][kk] * rb[j];
            }
        }

        cp_wait<0>();
        __syncthreads();
    }

    float bb[8];
    #pragma unroll
    for (int j = 0; j < 8; j++) bb[j] = bexp[n0 + tx * 8 + j];

    #pragma unroll
    for (int i = 0; i < 8; i++) {
        int m = m0 + ty * 8 + i;
        if (MOE && m >= cnt) continue;
        #pragma unroll
        for (int j = 0; j < 8; j++) {
            float v = acc[i][j] + bb[j];
            int n = n0 + tx * 8 + j;
            if (FIRST) {
                v = 0.5f * v * (1.f + erff(v * 0.70710678118654752f));
                if (MOE) g_h[((size_t)e * TT + m) * HH + n] = v;
                else     g_hs[(size_t)m * HH + n] = v;
            } else {
                if (MOE) {
                    atomicAdd(&out[(size_t)s_tok[ty * 8 + i] * DD + n],
                              s_wt[ty * 8 + i] * v);
                } else {
                    out[(size_t)m * DD + n] = v;
                }
            }
        }
    }
}

// ---------------- finalize ----------------
__global__ void finalize_k(float* __restrict__ out, int out_size) {
    if (blockIdx.x == 0 && threadIdx.x == 0) {
        float aux = 0.f;
        for (int e = 0; e < EE; e++) {
            float P = g_psum[e] / (float)TT;
            float F = (float)EE * (float)g_cnt[e] / (float)(KTOP * TT);
            aux += P * F;
        }
        const int base = TT * DD;
        if (out_size >= base + 1) out[base] = aux;
        for (int e = 0; e < EE; e++)
            if (out_size >= base + 2 + e) out[base + 1 + e] = (float)g_cnt[e];
    }
}

extern "C" void kernel_launch(void* const* d_in, const int* in_sizes, int n_in,
                              void* d_out, int out_size) {
    const float* x    = (const float*)d_in[0];
    const float* gW   = (const float*)d_in[1];
    const float* gb   = (const float*)d_in[2];
    const float* bias = (const float*)d_in[3];
    const float* W1   = (const float*)d_in[4];
    const float* b1   = (const float*)d_in[5];
    const float* W2   = (const float*)d_in[6];
    const float* b2   = (const float*)d_in[7];
    const float* sW1  = (const float*)d_in[8];
    const float* sb1  = (const float*)d_in[9];
    const float* sW2  = (const float*)d_in[10];
    const float* sb2  = (const float*)d_in[11];
    float* out = (float*)d_out;

    zero_k<<<1, 32>>>();
    gating_k<<<TT, 736>>>(x, gW, gb, bias);

    ffn_k<true, true><<<dim3(HH / 128, TT / 128, EE), 256>>>(x, W1, b1, nullptr);
    ffn_k<false, true><<<dim3(HH / 128, TT / 128, 1), 256>>>(x, sW1, sb1, nullptr);
    ffn_k<false, false><<<dim3(DD / 128, TT / 128, 1), 256>>>(nullptr, sW2, sb2, out);
    ffn_k<true, false><<<dim3(DD / 128, TT / 128, EE), 256>>>(nullptr, W2, b2, out);

    finalize_k<<<1, 32>>>(out, out_size);
}